// round 4
// baseline (speedup 1.0000x reference)
#include <cuda_runtime.h>
#include <cstdint>

// SimpleSparseConvNet: rulebook sparse conv, Cin=1, Cout=16.
// Degree-aware scatter, quad-lane layout: 4 consecutive lanes cooperate on one
// rulebook pair, each lane owning one float4 quad of the 16-float output row.
// This makes output stores/atomics warp-coalesced (8 rows x 64B per warp instr).

#define MAX_NOUT (4 * 1024 * 1024)

__device__ unsigned int g_counts[MAX_NOUT];

__device__ __forceinline__ void red_add_v4(float* addr, float a, float b, float c, float d) {
    asm volatile("red.global.add.v4.f32 [%0], {%1, %2, %3, %4};"
                 :: "l"(addr), "f"(a), "f"(b), "f"(c), "f"(d)
                 : "memory");
}

// ---- K0: zero counts --------------------------------------------------------
__global__ void __launch_bounds__(256)
k_zero_counts(int n4) {
    int i = blockIdx.x * blockDim.x + threadIdx.x;
    if (i < n4) reinterpret_cast<uint4*>(g_counts)[i] = make_uint4(0, 0, 0, 0);
}

// ---- K1: histogram of out_idx -----------------------------------------------
__global__ void __launch_bounds__(256)
k_count(const int* __restrict__ out_idx, int M) {
    int m = blockIdx.x * blockDim.x + threadIdx.x;
    if (m < M) atomicAdd(&g_counts[out_idx[m]], 1u);
}

// ---- K2: zero output rows with deg >= 2 (thread per float4, coalesced) ------
__global__ void __launch_bounds__(256)
k_zero_multi(float* __restrict__ out, int n_out) {
    int tid = blockIdx.x * blockDim.x + threadIdx.x;
    int o = tid >> 2;
    if (o >= n_out) return;
    if (g_counts[o] >= 2u) {
        reinterpret_cast<float4*>(out)[tid] = make_float4(0.f, 0.f, 0.f, 0.f);
    }
}

// ---- K3: degree-aware scatter, 4 lanes per pair ------------------------------
__global__ void __launch_bounds__(256)
k_scatter(const float* __restrict__ feats,
          const float* __restrict__ weight,
          const int* __restrict__ in_idx,
          const int* __restrict__ out_idx,
          const int* __restrict__ k_idx,
          float* __restrict__ out,
          int M) {
    int tid = blockIdx.x * blockDim.x + threadIdx.x;
    int m = tid >> 2;
    int j = tid & 3;
    if (m >= M) return;

    // Quad-broadcast loads (4 lanes hit the same address; L1 broadcasts)
    const int o = __ldg(&out_idx[m]);
    const int k = __ldg(&k_idx[m]);
    const float f = __ldg(&feats[__ldg(&in_idx[m])]);
    const unsigned int deg = g_counts[o];

    float4 w = __ldg(reinterpret_cast<const float4*>(weight) + (size_t)k * 4 + j);
    float4 v = make_float4(f * w.x, f * w.y, f * w.z, f * w.w);
    float* op = out + (size_t)o * 16 + j * 4;

    if (deg == 1u) {
        *reinterpret_cast<float4*>(op) = v;     // exclusive owner: plain store
    } else {
        red_add_v4(op, v.x, v.y, v.z, v.w);     // accumulate
    }
}

extern "C" void kernel_launch(void* const* d_in, const int* in_sizes, int n_in,
                              void* d_out, int out_size) {
    const float* feats  = (const float*)d_in[0];
    const float* weight = (const float*)d_in[1];
    const int* in_idx   = (const int*)d_in[2];
    const int* out_idx  = (const int*)d_in[3];
    const int* k_idx    = (const int*)d_in[4];
    float* out = (float*)d_out;

    const int M = in_sizes[2];
    const int n_out = out_size / 16;

    const int T = 256;
    const int n4 = (n_out + 3) / 4;

    k_zero_counts<<<(n4 + T - 1) / T, T>>>(n4);
    k_count<<<(M + T - 1) / T, T>>>(out_idx, M);
    k_zero_multi<<<((n_out * 4) + T - 1) / T, T>>>(out, n_out);
    k_scatter<<<((size_t)M * 4 + T - 1) / T, T>>>(feats, weight, in_idx, out_idx, k_idx, out, M);
}

// round 5
// speedup vs baseline: 1.1275x; 1.1275x over previous
#include <cuda_runtime.h>
#include <cstdint>

// SimpleSparseConvNet: rulebook sparse conv, Cin=1, Cout=16.
// Quad-lane degree-aware scatter with 2 pairs per quad (front-batched loads
// for MLP). deg==1 rows: plain STG.128. deg>=2 rows: zeroed, then red.v4.

#define MAX_NOUT (4 * 1024 * 1024)

__device__ unsigned int g_counts[MAX_NOUT];

__device__ __forceinline__ void red_add_v4(float* addr, float a, float b, float c, float d) {
    asm volatile("red.global.add.v4.f32 [%0], {%1, %2, %3, %4};"
                 :: "l"(addr), "f"(a), "f"(b), "f"(c), "f"(d)
                 : "memory");
}

// ---- K0: zero counts --------------------------------------------------------
__global__ void __launch_bounds__(256)
k_zero_counts(int n4) {
    int i = blockIdx.x * blockDim.x + threadIdx.x;
    if (i < n4) reinterpret_cast<uint4*>(g_counts)[i] = make_uint4(0, 0, 0, 0);
}

// ---- K1: histogram of out_idx -----------------------------------------------
__global__ void __launch_bounds__(256)
k_count(const int* __restrict__ out_idx, int M) {
    int m = blockIdx.x * blockDim.x + threadIdx.x;
    if (m < M) atomicAdd(&g_counts[out_idx[m]], 1u);
}

// ---- K2: zero output rows with deg >= 2 (thread per float4, coalesced) ------
__global__ void __launch_bounds__(256)
k_zero_multi(float* __restrict__ out, int n_out) {
    int tid = blockIdx.x * blockDim.x + threadIdx.x;
    int o = tid >> 2;
    if (o >= n_out) return;
    if (__ldg(&g_counts[o]) >= 2u) {
        reinterpret_cast<float4*>(out)[tid] = make_float4(0.f, 0.f, 0.f, 0.f);
    }
}

// ---- K3: scatter, 4 lanes per pair, 2 pairs per quad -------------------------
__global__ void __launch_bounds__(256)
k_scatter(const float* __restrict__ feats,
          const float* __restrict__ weight,
          const int* __restrict__ in_idx,
          const int* __restrict__ out_idx,
          const int* __restrict__ k_idx,
          float* __restrict__ out,
          int M, int Q) {
    int tid = blockIdx.x * blockDim.x + threadIdx.x;
    int q = tid >> 2;
    int j = tid & 3;
    if (q >= Q) return;

    const int m0 = q;
    const int m1 = q + Q;
    const bool v1 = (m1 < M);

    // ---- front-batched independent loads (maximize MLP) ----
    const int o0 = __ldg(&out_idx[m0]);
    const int k0 = __ldg(&k_idx[m0]);
    const int i0 = __ldg(&in_idx[m0]);
    int o1 = 0, k1 = 0, i1 = 0;
    if (v1) {
        o1 = __ldg(&out_idx[m1]);
        k1 = __ldg(&k_idx[m1]);
        i1 = __ldg(&in_idx[m1]);
    }

    const float f0 = __ldg(&feats[i0]);
    const unsigned int d0 = __ldg(&g_counts[o0]);
    const float4 w0 = __ldg(reinterpret_cast<const float4*>(weight) + (size_t)k0 * 4 + j);

    float f1 = 0.f;
    unsigned int d1 = 0;
    float4 w1 = make_float4(0.f, 0.f, 0.f, 0.f);
    if (v1) {
        f1 = __ldg(&feats[i1]);
        d1 = __ldg(&g_counts[o1]);
        w1 = __ldg(reinterpret_cast<const float4*>(weight) + (size_t)k1 * 4 + j);
    }

    // ---- pair 0 ----
    {
        float4 v = make_float4(f0 * w0.x, f0 * w0.y, f0 * w0.z, f0 * w0.w);
        float* op = out + (size_t)o0 * 16 + j * 4;
        if (d0 == 1u) *reinterpret_cast<float4*>(op) = v;
        else          red_add_v4(op, v.x, v.y, v.z, v.w);
    }
    // ---- pair 1 ----
    if (v1) {
        float4 v = make_float4(f1 * w1.x, f1 * w1.y, f1 * w1.z, f1 * w1.w);
        float* op = out + (size_t)o1 * 16 + j * 4;
        if (d1 == 1u) *reinterpret_cast<float4*>(op) = v;
        else          red_add_v4(op, v.x, v.y, v.z, v.w);
    }
}

extern "C" void kernel_launch(void* const* d_in, const int* in_sizes, int n_in,
                              void* d_out, int out_size) {
    const float* feats  = (const float*)d_in[0];
    const float* weight = (const float*)d_in[1];
    const int* in_idx   = (const int*)d_in[2];
    const int* out_idx  = (const int*)d_in[3];
    const int* k_idx    = (const int*)d_in[4];
    float* out = (float*)d_out;

    const int M = in_sizes[2];
    const int n_out = out_size / 16;
    const int Q = (M + 1) / 2;          // quads (2 pairs each)

    const int T = 256;
    const int n4 = (n_out + 3) / 4;

    k_zero_counts<<<(n4 + T - 1) / T, T>>>(n4);
    k_count<<<(M + T - 1) / T, T>>>(out_idx, M);
    k_zero_multi<<<((size_t)n_out * 4 + T - 1) / T, T>>>(out, n_out);
    k_scatter<<<((size_t)Q * 4 + T - 1) / T, T>>>(feats, weight, in_idx, out_idx,
                                                  k_idx, out, M, Q);
}